// round 12
// baseline (speedup 1.0000x reference)
#include <cuda_runtime.h>

#define B_    16
#define N_    400
#define P_    200
#define E_D   200
#define A_D   128
#define H_    8
#define PT    4      // pathways per block in kernel B
#define NCH   7      // gene chunks of 64 (6 full + 1 partial of 16)

typedef unsigned long long u64;

// proj scratch: ulonglong2 at ((b*NCH + c)*64 + k)*32 + lane =
//   { u64(prj[gLo][2k],  prj[gHi][2k]),  u64(prj[gLo][2k+1], prj[gHi][2k+1]) }
// gLo = c*64+lane, gHi = gLo+32 (c<6); chunk 6: lane<8, gLo=384+lane, gHi=gLo+8.
__device__ ulonglong2 g_projP[B_ * NCH * 64 * 32];

// attn scratch (B, P, N) written by kB phase 2, consumed by kC.
__device__ float g_attn[B_ * P_ * N_];

// Wb duplicated pairs: staging (device) -> constant (LDC port, off L1).
__device__ u64 g_wbDup[A_D * H_];             // [a*8 + h] = (w, w)
__constant__ ulonglong2 c_wb4[A_D * H_ / 2];  // [a*4 + h2]: .x=head 2h2, .y=head 2h2+1

__device__ __forceinline__ u64 pack2(float x, float y) {
    u64 r; asm("mov.b64 %0, {%1, %2};" : "=l"(r) : "f"(x), "f"(y)); return r;
}
__device__ __forceinline__ void unpack2(u64 v, float& x, float& y) {
    asm("mov.b64 {%0, %1}, %2;" : "=f"(x), "=f"(y) : "l"(v));
}
__device__ __forceinline__ u64 fma2(u64 a, u64 b, u64 c) {
    u64 d; asm("fma.rn.f32x2 %0, %1, %2, %3;" : "=l"(d) : "l"(a), "l"(b), "l"(c)); return d;
}
__device__ __forceinline__ u64 add2(u64 a, u64 b) {
    u64 d; asm("add.rn.f32x2 %0, %1, %2;" : "=l"(d) : "l"(a), "l"(b)); return d;
}
__device__ __forceinline__ float tanh_ap(float x) {
    float y; asm("tanh.approx.f32 %0, %1;" : "=f"(y) : "f"(x)); return y;
}
__device__ __forceinline__ u64 tanh2(u64 v) {
    float x, y; unpack2(v, x, y);
    return pack2(tanh_ap(x), tanh_ap(y));
}

// ---------------------------------------------------------------------------
// Kernel W: duplicate Wb scalars into (w,w) pairs for f32x2 FMAs.
// ---------------------------------------------------------------------------
__global__ void kW(const float* __restrict__ Wb)
{
    int i = blockIdx.x * 256 + threadIdx.x;
    if (i < A_D * H_) {
        float v = Wb[i];
        g_wbDup[i] = pack2(v, v);
    }
}

// ---------------------------------------------------------------------------
// Kernel A: proj = emb_gene[omc] @ W0 + b0, scattered into gene-paired layout.
// ---------------------------------------------------------------------------
__global__ __launch_bounds__(128) void kA(
    const int* __restrict__ omc, const float* __restrict__ eg,
    const float* __restrict__ W0, const float* __restrict__ b0)
{
    __shared__ float EsT[E_D * 8];   // [e][r]
    __shared__ int idxs[8];
    const int R0 = blockIdx.x * 8;
    const int b  = R0 / N_;
    const int nb = R0 - b * N_;
    const int t  = threadIdx.x;

    if (t < 8) idxs[t] = omc[R0 + t];
    __syncthreads();
    for (int i = t; i < 8 * E_D; i += 128) {
        int r = i / E_D, e = i - r * E_D;
        EsT[e * 8 + r] = eg[(long)idxs[r] * E_D + e];
    }
    __syncthreads();

    const int k  = t & 63;           // a-pair: a = 2k, 2k+1
    const int rg = t >> 6;           // row group (4 rows each)
    const u64* W2 = (const u64*)W0;  // [e][64] pairs
    const u64  bias = ((const u64*)b0)[k];

    u64 acc[4];
#pragma unroll
    for (int r = 0; r < 4; r++) acc[r] = bias;

#pragma unroll 4
    for (int e = 0; e < E_D; e++) {
        u64 w = W2[e * 64 + k];
        const float* er = EsT + e * 8 + rg * 4;
        acc[0] = fma2(pack2(er[0], er[0]), w, acc[0]);
        acc[1] = fma2(pack2(er[1], er[1]), w, acc[1]);
        acc[2] = fma2(pack2(er[2], er[2]), w, acc[2]);
        acc[3] = fma2(pack2(er[3], er[3]), w, acc[3]);
    }

    float* pf = (float*)g_projP;
#pragma unroll
    for (int r = 0; r < 4; r++) {
        const int n = nb + rg * 4 + r;          // gene index within batch b
        const int chunk = n >> 6;
        const int idx   = n & 63;
        int lane, comp;
        if (chunk < 6) { lane = idx & 31; comp = idx >> 5; }
        else           { lane = idx & 7;  comp = idx >> 3; }
        // float layout of ulonglong2 cell: {aLo.gLo, aLo.gHi, aHi.gLo, aHi.gHi}
        const int fbase = (((b * NCH + chunk) * 64 + k) * 32 + lane) * 4 + comp;
        float x, y;
        unpack2(acc[r], x, y);
        pf[fbase]     = x;      // a = 2k
        pf[fbase + 2] = y;      // a = 2k+1
    }
}

// ---------------------------------------------------------------------------
// Kernel B (scores + softmax). Block = (b, 4 pathways), 256 threads, 8 warps.
// Phase 1: warp -> pathway PAIR (w&1), chunk slots (w>>1): c, c+4.
//          Pipelined stages; Wb from constant (LDC); writes scores to smem.
// Phase 2: softmax per head, head-sum -> attn written to GLOBAL g_attn.
// No pooling here (kC does it) -> no gather staging, no barrier storm.
//
// SMEM floats:
//   sc    [0, 12800)       scores PT*H*N
//   epsQ  [12800, 13824)   2 groups x 128 a x {dupA u64, dupB u64}
//   sinv  [13824, 13856)
//   bbs   [13856, 13864)
// = 55456 bytes -> 3 blocks/SM (regs are the binding limit)
// ---------------------------------------------------------------------------
#define SMEM_B_FLOATS 13864
#define SMEM_B_BYTES  (SMEM_B_FLOATS * 4)

extern __shared__ float smemB[];

#define STAGE_FMA(wc, T0, T1, T2, T3)                                   \
    do {                                                                \
        ulonglong2 wA = c_wb4[(wc) + 0];                                \
        accA[0] = fma2(T0, wA.x, accA[0]);                              \
        accB[0] = fma2(T1, wA.x, accB[0]);                              \
        accA[1] = fma2(T0, wA.y, accA[1]);                              \
        accB[1] = fma2(T1, wA.y, accB[1]);                              \
        ulonglong2 wB = c_wb4[(wc) + 1];                                \
        accA[2] = fma2(T0, wB.x, accA[2]);                              \
        accB[2] = fma2(T1, wB.x, accB[2]);                              \
        accA[3] = fma2(T0, wB.y, accA[3]);                              \
        accB[3] = fma2(T1, wB.y, accB[3]);                              \
        ulonglong2 wC = c_wb4[(wc) + 2];                                \
        accA[4] = fma2(T0, wC.x, accA[4]);                              \
        accB[4] = fma2(T1, wC.x, accB[4]);                              \
        accA[5] = fma2(T0, wC.y, accA[5]);                              \
        accB[5] = fma2(T1, wC.y, accB[5]);                              \
        ulonglong2 wD = c_wb4[(wc) + 3];                                \
        accA[6] = fma2(T0, wD.x, accA[6]);                              \
        accB[6] = fma2(T1, wD.x, accB[6]);                              \
        accA[7] = fma2(T0, wD.y, accA[7]);                              \
        accB[7] = fma2(T1, wD.y, accB[7]);                              \
        ulonglong2 wE = c_wb4[(wc) + 4];                                \
        accA[0] = fma2(T2, wE.x, accA[0]);                              \
        accB[0] = fma2(T3, wE.x, accB[0]);                              \
        accA[1] = fma2(T2, wE.y, accA[1]);                              \
        accB[1] = fma2(T3, wE.y, accB[1]);                              \
        ulonglong2 wF = c_wb4[(wc) + 5];                                \
        accA[2] = fma2(T2, wF.x, accA[2]);                              \
        accB[2] = fma2(T3, wF.x, accB[2]);                              \
        accA[3] = fma2(T2, wF.y, accA[3]);                              \
        accB[3] = fma2(T3, wF.y, accB[3]);                              \
        ulonglong2 wG = c_wb4[(wc) + 6];                                \
        accA[4] = fma2(T2, wG.x, accA[4]);                              \
        accB[4] = fma2(T3, wG.x, accB[4]);                              \
        accA[5] = fma2(T2, wG.y, accA[5]);                              \
        accB[5] = fma2(T3, wG.y, accB[5]);                              \
        ulonglong2 wH = c_wb4[(wc) + 7];                                \
        accA[6] = fma2(T2, wH.x, accA[6]);                              \
        accB[6] = fma2(T3, wH.x, accB[6]);                              \
        accA[7] = fma2(T2, wH.y, accA[7]);                              \
        accB[7] = fma2(T3, wH.y, accB[7]);                              \
    } while (0)

#define STAGE_TANH(L, epB, D0, D1, D2, D3)                              \
    do {                                                                \
        ulonglong2 e0 = *(const ulonglong2*)(epB);                      \
        D0 = tanh2(add2((L).x, e0.x));                                  \
        D1 = tanh2(add2((L).x, e0.y));                                  \
        ulonglong2 e1 = *(const ulonglong2*)((epB) + 16);               \
        D2 = tanh2(add2((L).y, e1.x));                                  \
        D3 = tanh2(add2((L).y, e1.y));                                  \
    } while (0)

__global__ __launch_bounds__(256, 3) void kB(
    const int* __restrict__ ptw, const float* __restrict__ ept,
    const float* __restrict__ bb)
{
    float* sc   = smemB;
    ulonglong2* epsQ = (ulonglong2*)(smemB + 12800);  // [group*128 + a]
    float* sinv = smemB + 13824;
    float* bbs  = smemB + 13856;

    const int bx   = blockIdx.x;
    const int b    = bx / 50;
    const int pt   = bx - b * 50;
    const int t    = threadIdx.x;
    const int w    = t >> 5;
    const int lane = t & 31;

    // ---- init loads -------------------------------------------------------
    {
        float* ef = (float*)epsQ;
        for (int i = t; i < 1024; i += 256) {
            int g  = i >> 9;            // group 0..1
            int a  = (i >> 2) & 127;
            int c4 = i & 3;             // 0,1 -> dupA; 2,3 -> dupB
            int pl = g * 2 + (c4 >> 1);
            ef[(g * 128 + a) * 4 + c4] = ept[(long)ptw[pt * PT + pl] * A_D + a];
        }
    }
    if (t < 8) bbs[t] = bb[t];
    __syncthreads();

    // ---- Phase 1: scores, pipelined stages, Wb from constant --------------
    {
        const int pairI = w & 1;             // pathways 2*pairI, 2*pairI+1
        float* scA = sc + (2 * pairI + 0) * H_ * N_;
        float* scB = sc + (2 * pairI + 1) * H_ * N_;
        const char* epBase = (const char*)(epsQ + pairI * 128);

        for (int c = w >> 1; c < NCH; c += 4) {
            u64 accA[H_], accB[H_];
#pragma unroll
            for (int h = 0; h < H_; h++) { accA[h] = 0ull; accB[h] = 0ull; }

            const char* ppB = (const char*)(g_projP + ((b * NCH + c) * 64) * 32 + lane);
            const char* epB = epBase;          // ep for stage s+1 inside loop

            u64 T0, T1, T2, T3, U0, U1, U2, U3;
            {
                ulonglong2 L0 = *(const ulonglong2*)ppB;
                STAGE_TANH(L0, epB, T0, T1, T2, T3);
            }
            ulonglong2 L1 = *(const ulonglong2*)(ppB + 512);
            ulonglong2 L2 = *(const ulonglong2*)(ppB + 1024);
            ppB += 1536;
            epB += 32;

            int wc = 0;
#pragma unroll 2
            for (int s = 0; s < 62; s++) {
                STAGE_TANH(L1, epB, U0, U1, U2, U3);     // tanh for s+1
                STAGE_FMA(wc, T0, T1, T2, T3);           // FMA  for s
                L1 = L2;
                L2 = *(const ulonglong2*)ppB;            // load s+3
                T0 = U0; T1 = U1; T2 = U2; T3 = U3;
                ppB += 512;
                epB += 32;
                wc += 8;
            }
            STAGE_TANH(L1, epB, U0, U1, U2, U3);
            STAGE_FMA(wc, T0, T1, T2, T3);
            STAGE_FMA(wc + 8, U0, U1, U2, U3);

            int geneA, geneB;
            bool valid;
            if (c < 6) { geneA = c * 64 + lane; geneB = geneA + 32; valid = true; }
            else       { geneA = 384 + (lane & 7); geneB = geneA + 8; valid = (lane < 8); }
            if (valid) {
#pragma unroll
                for (int h = 0; h < H_; h++) {
                    float xA, yA, xB, yB;
                    unpack2(accA[h], xA, yA);
                    unpack2(accB[h], xB, yB);
                    const float bh = bbs[h];
                    scA[h * N_ + geneA] = xA + bh;
                    scA[h * N_ + geneB] = yA + bh;
                    scB[h * N_ + geneA] = xB + bh;
                    scB[h * N_ + geneB] = yB + bh;
                }
            }
        }
    }
    __syncthreads();

    // ---- Phase 2: softmax over n per head; attn = sum_h -> g_attn ---------
    const int p    = w >> 1;
    const int half = w & 1;
    const int pg   = pt * PT + p;
    float* scp = sc + p * H_ * N_;
#pragma unroll
    for (int q = 0; q < 4; q++) {
        const int h = half * 4 + q;
        float* row = scp + h * N_;
        float m = -1e30f;
        for (int i = lane; i < N_; i += 32) m = fmaxf(m, row[i]);
#pragma unroll
        for (int o = 16; o; o >>= 1) m = fmaxf(m, __shfl_xor_sync(0xffffffffu, m, o));
        float s = 0.f;
        for (int i = lane; i < N_; i += 32) {
            float e = __expf(row[i] - m);
            row[i] = e;
            s += e;
        }
#pragma unroll
        for (int o = 16; o; o >>= 1) s += __shfl_xor_sync(0xffffffffu, s, o);
        if (lane == 0) sinv[p * H_ + h] = __fdividef(1.f, s);
    }
    __syncthreads();

    {
        float iv[H_];
#pragma unroll
        for (int h = 0; h < H_; h++) iv[h] = sinv[p * H_ + h];
        float* gap = g_attn + ((long)(b * P_) + pg) * N_;
        for (int i = lane; i < 200; i += 32) {
            const int n = half * 200 + i;
            float a = 0.f;
#pragma unroll
            for (int h = 0; h < H_; h++) a = fmaf(scp[h * N_ + n], iv[h], a);
            gap[n] = a;
        }
    }
}

// ---------------------------------------------------------------------------
// Kernel C (pooling): out[b,pg,:] = sum_n attn[b,pg,n] * E[b,n,:]
// Block = (b, 8 pathways), 512 threads = 16 warps; warp = (pathway, E-half).
// E chunk (64 genes x 200 floats) staged once per block (halves the gather
// redundancy vs doing it inside kB's 800 blocks).
//
// SMEM floats:
//   Es    [0, 12800)       64 x 200
//   attnS [12800, 16000)   8 x 400
//   idxs  [16000, 16064)
// = 64256 bytes -> 3 blocks/SM; 48 warps.
// ---------------------------------------------------------------------------
#define SMEM_C_FLOATS 16064
#define SMEM_C_BYTES  (SMEM_C_FLOATS * 4)

__global__ __launch_bounds__(512, 3) void kC(
    const int* __restrict__ omc, const float* __restrict__ eg,
    float* __restrict__ out)
{
    float* Es    = smemB;               // reuse extern smem symbol
    float* attnS = smemB + 12800;
    int*   idxs  = (int*)(smemB + 16000);

    const int bx   = blockIdx.x;
    const int b    = bx / 25;
    const int pt8  = bx - b * 25;       // pathway octet
    const int t    = threadIdx.x;
    const int w    = t >> 5;
    const int lane = t & 31;
    const int p    = w >> 1;            // 0..7 within octet
    const int half = w & 1;
    const int pg   = pt8 * 8 + p;

    // attn for 8 pathways: 3200 contiguous floats
    {
        const float4* gA0 = (const float4*)(g_attn + ((long)(b * P_) + pt8 * 8) * N_);
        float4* aS = (float4*)attnS;
        for (int i = t; i < 800; i += 512) aS[i] = gA0[i];
    }

    const ulonglong2* eg4 = (const ulonglong2*)eg;   // 50 per vocab row
    ulonglong2* Es4 = (ulonglong2*)Es;
    const float* ap = attnS + p * N_;
    const int j0 = half * 50;                        // E-slice in u64 units
    u64 acc0 = 0ull, acc1 = 0ull;

    for (int c = 0; c < 7; c++) {
        const int n0 = c * 64;
        const int cnt = min(64, N_ - n0);
        __syncthreads();
        if (t < cnt) idxs[t] = omc[b * N_ + n0 + t];
        __syncthreads();
        for (int i = t; i < cnt * 50; i += 512) {
            int n = i / 50, e4 = i - n * 50;
            Es4[n * 50 + e4] = eg4[(long)idxs[n] * 50 + e4];
        }
        __syncthreads();

        const u64* Esu = (const u64*)Es4;
#pragma unroll 2
        for (int n = 0; n < cnt; n++) {
            float a = ap[n0 + n];
            u64 av = pack2(a, a);
            const u64* er = Esu + n * 100;
            acc0 = fma2(er[j0 + lane], av, acc0);
            if (lane < 18) acc1 = fma2(er[j0 + 32 + lane], av, acc1);
        }
    }

    u64* op = (u64*)out + (long)(b * P_ + pg) * 100;
    op[j0 + lane] = acc0;
    if (lane < 18) op[j0 + 32 + lane] = acc1;
}

// ---------------------------------------------------------------------------
extern "C" void kernel_launch(void* const* d_in, const int* in_sizes, int n_in,
                              void* d_out, int out_size)
{
    const int*   omc = (const int*)  d_in[0];
    const int*   ptw = (const int*)  d_in[1];
    const float* eg  = (const float*)d_in[2];
    const float* ept = (const float*)d_in[3];
    const float* W0  = (const float*)d_in[4];
    const float* b0  = (const float*)d_in[5];
    const float* Wb  = (const float*)d_in[6];
    const float* bb  = (const float*)d_in[7];
    float* out = (float*)d_out;

    // Wb -> duplicated pairs (device staging) -> constant bank (d2d).
    kW<<<4, 256>>>(Wb);
    void* srcp = nullptr;
    cudaGetSymbolAddress(&srcp, g_wbDup);
    void* dstp = nullptr;
    cudaGetSymbolAddress(&dstp, c_wb4);
    cudaMemcpyAsync(dstp, srcp, sizeof(u64) * A_D * H_,
                    cudaMemcpyDeviceToDevice, 0);

    kA<<<(B_ * N_) / 8, 128>>>(omc, eg, W0, b0);

    cudaFuncSetAttribute(kB, cudaFuncAttributeMaxDynamicSharedMemorySize,
                         SMEM_B_BYTES);
    kB<<<B_ * (P_ / PT), 256, SMEM_B_BYTES>>>(ptw, ept, bb);

    cudaFuncSetAttribute(kC, cudaFuncAttributeMaxDynamicSharedMemorySize,
                         SMEM_C_BYTES);
    kC<<<B_ * (P_ / 8), 512, SMEM_C_BYTES>>>(omc, eg, out);
}

// round 13
// speedup vs baseline: 1.1502x; 1.1502x over previous
#include <cuda_runtime.h>

#define B_    16
#define N_    400
#define P_    200
#define E_D   200
#define A_D   128
#define H_    8
#define PT    4      // pathways per block in kernel B
#define NCH   7      // gene chunks of 64 (6 full + 1 partial of 16)

typedef unsigned long long u64;

// proj scratch: ulonglong2 at ((b*NCH + c)*64 + k)*32 + lane =
//   { u64(prj[gLo][2k],  prj[gHi][2k]),  u64(prj[gLo][2k+1], prj[gHi][2k+1]) }
// gLo = c*64+lane, gHi = gLo+32 (c<6); chunk 6: lane<8, gLo=384+lane, gHi=gLo+8.
__device__ ulonglong2 g_projP[B_ * NCH * 64 * 32];

// attn scratch (B, P, N) written by kB phase 2, consumed by kC.
__device__ float g_attn[B_ * P_ * N_];

// Wb duplicated pairs: staging (device) -> constant (LDC port, off L1).
__device__ u64 g_wbDup[A_D * H_];             // [a*8 + h] = (w, w)
__constant__ ulonglong2 c_wb4[A_D * H_ / 2];  // [a*4 + h2]: .x=head 2h2, .y=head 2h2+1

__device__ __forceinline__ u64 pack2(float x, float y) {
    u64 r; asm("mov.b64 %0, {%1, %2};" : "=l"(r) : "f"(x), "f"(y)); return r;
}
__device__ __forceinline__ void unpack2(u64 v, float& x, float& y) {
    asm("mov.b64 {%0, %1}, %2;" : "=f"(x), "=f"(y) : "l"(v));
}
__device__ __forceinline__ u64 fma2(u64 a, u64 b, u64 c) {
    u64 d; asm("fma.rn.f32x2 %0, %1, %2, %3;" : "=l"(d) : "l"(a), "l"(b), "l"(c)); return d;
}
__device__ __forceinline__ u64 add2(u64 a, u64 b) {
    u64 d; asm("add.rn.f32x2 %0, %1, %2;" : "=l"(d) : "l"(a), "l"(b)); return d;
}
__device__ __forceinline__ float tanh_ap(float x) {
    float y; asm("tanh.approx.f32 %0, %1;" : "=f"(y) : "f"(x)); return y;
}
__device__ __forceinline__ u64 tanh2(u64 v) {
    float x, y; unpack2(v, x, y);
    return pack2(tanh_ap(x), tanh_ap(y));
}

// ---------------------------------------------------------------------------
// Kernel W: duplicate Wb scalars into (w,w) pairs for f32x2 FMAs.
// ---------------------------------------------------------------------------
__global__ void kW(const float* __restrict__ Wb)
{
    int i = blockIdx.x * 256 + threadIdx.x;
    if (i < A_D * H_) {
        float v = Wb[i];
        g_wbDup[i] = pack2(v, v);
    }
}

// ---------------------------------------------------------------------------
// Kernel A: proj = emb_gene[omc] @ W0 + b0, scattered into gene-paired layout.
// ---------------------------------------------------------------------------
__global__ __launch_bounds__(128) void kA(
    const int* __restrict__ omc, const float* __restrict__ eg,
    const float* __restrict__ W0, const float* __restrict__ b0)
{
    __shared__ float EsT[E_D * 8];   // [e][r]
    __shared__ int idxs[8];
    const int R0 = blockIdx.x * 8;
    const int b  = R0 / N_;
    const int nb = R0 - b * N_;
    const int t  = threadIdx.x;

    if (t < 8) idxs[t] = omc[R0 + t];
    __syncthreads();
    for (int i = t; i < 8 * E_D; i += 128) {
        int r = i / E_D, e = i - r * E_D;
        EsT[e * 8 + r] = eg[(long)idxs[r] * E_D + e];
    }
    __syncthreads();

    const int k  = t & 63;           // a-pair: a = 2k, 2k+1
    const int rg = t >> 6;           // row group (4 rows each)
    const u64* W2 = (const u64*)W0;  // [e][64] pairs
    const u64  bias = ((const u64*)b0)[k];

    u64 acc[4];
#pragma unroll
    for (int r = 0; r < 4; r++) acc[r] = bias;

#pragma unroll 4
    for (int e = 0; e < E_D; e++) {
        u64 w = W2[e * 64 + k];
        const float* er = EsT + e * 8 + rg * 4;
        acc[0] = fma2(pack2(er[0], er[0]), w, acc[0]);
        acc[1] = fma2(pack2(er[1], er[1]), w, acc[1]);
        acc[2] = fma2(pack2(er[2], er[2]), w, acc[2]);
        acc[3] = fma2(pack2(er[3], er[3]), w, acc[3]);
    }

    float* pf = (float*)g_projP;
#pragma unroll
    for (int r = 0; r < 4; r++) {
        const int n = nb + rg * 4 + r;          // gene index within batch b
        const int chunk = n >> 6;
        const int idx   = n & 63;
        int lane, comp;
        if (chunk < 6) { lane = idx & 31; comp = idx >> 5; }
        else           { lane = idx & 7;  comp = idx >> 3; }
        // float layout of ulonglong2 cell: {aLo.gLo, aLo.gHi, aHi.gLo, aHi.gHi}
        const int fbase = (((b * NCH + chunk) * 64 + k) * 32 + lane) * 4 + comp;
        float x, y;
        unpack2(acc[r], x, y);
        pf[fbase]     = x;      // a = 2k
        pf[fbase + 2] = y;      // a = 2k+1
    }
}

// ---------------------------------------------------------------------------
// Kernel B (scores + softmax). Block = (b, 4 pathways), 256 threads, 8 warps.
// Identical to R12's kB (measured in the 144.8us kW+kA+kB aggregate).
//
// SMEM floats:
//   sc    [0, 12800)       scores PT*H*N
//   epsQ  [12800, 13824)   2 groups x 128 a x {dupA u64, dupB u64}
//   sinv  [13824, 13856)
//   bbs   [13856, 13864)
// = 55456 bytes
// ---------------------------------------------------------------------------
#define SMEM_B_FLOATS 13864
#define SMEM_B_BYTES  (SMEM_B_FLOATS * 4)

extern __shared__ float smemB[];

#define STAGE_FMA(wc, T0, T1, T2, T3)                                   \
    do {                                                                \
        ulonglong2 wA = c_wb4[(wc) + 0];                                \
        accA[0] = fma2(T0, wA.x, accA[0]);                              \
        accB[0] = fma2(T1, wA.x, accB[0]);                              \
        accA[1] = fma2(T0, wA.y, accA[1]);                              \
        accB[1] = fma2(T1, wA.y, accB[1]);                              \
        ulonglong2 wB = c_wb4[(wc) + 1];                                \
        accA[2] = fma2(T0, wB.x, accA[2]);                              \
        accB[2] = fma2(T1, wB.x, accB[2]);                              \
        accA[3] = fma2(T0, wB.y, accA[3]);                              \
        accB[3] = fma2(T1, wB.y, accB[3]);                              \
        ulonglong2 wC = c_wb4[(wc) + 2];                                \
        accA[4] = fma2(T0, wC.x, accA[4]);                              \
        accB[4] = fma2(T1, wC.x, accB[4]);                              \
        accA[5] = fma2(T0, wC.y, accA[5]);                              \
        accB[5] = fma2(T1, wC.y, accB[5]);                              \
        ulonglong2 wD = c_wb4[(wc) + 3];                                \
        accA[6] = fma2(T0, wD.x, accA[6]);                              \
        accB[6] = fma2(T1, wD.x, accB[6]);                              \
        accA[7] = fma2(T0, wD.y, accA[7]);                              \
        accB[7] = fma2(T1, wD.y, accB[7]);                              \
        ulonglong2 wE = c_wb4[(wc) + 4];                                \
        accA[0] = fma2(T2, wE.x, accA[0]);                              \
        accB[0] = fma2(T3, wE.x, accB[0]);                              \
        accA[1] = fma2(T2, wE.y, accA[1]);                              \
        accB[1] = fma2(T3, wE.y, accB[1]);                              \
        ulonglong2 wF = c_wb4[(wc) + 5];                                \
        accA[2] = fma2(T2, wF.x, accA[2]);                              \
        accB[2] = fma2(T3, wF.x, accB[2]);                              \
        accA[3] = fma2(T2, wF.y, accA[3]);                              \
        accB[3] = fma2(T3, wF.y, accB[3]);                              \
        ulonglong2 wG = c_wb4[(wc) + 6];                                \
        accA[4] = fma2(T2, wG.x, accA[4]);                              \
        accB[4] = fma2(T3, wG.x, accB[4]);                              \
        accA[5] = fma2(T2, wG.y, accA[5]);                              \
        accB[5] = fma2(T3, wG.y, accB[5]);                              \
        ulonglong2 wH = c_wb4[(wc) + 7];                                \
        accA[6] = fma2(T2, wH.x, accA[6]);                              \
        accB[6] = fma2(T3, wH.x, accB[6]);                              \
        accA[7] = fma2(T2, wH.y, accA[7]);                              \
        accB[7] = fma2(T3, wH.y, accB[7]);                              \
    } while (0)

#define STAGE_TANH(L, epB, D0, D1, D2, D3)                              \
    do {                                                                \
        ulonglong2 e0 = *(const ulonglong2*)(epB);                      \
        D0 = tanh2(add2((L).x, e0.x));                                  \
        D1 = tanh2(add2((L).x, e0.y));                                  \
        ulonglong2 e1 = *(const ulonglong2*)((epB) + 16);               \
        D2 = tanh2(add2((L).y, e1.x));                                  \
        D3 = tanh2(add2((L).y, e1.y));                                  \
    } while (0)

__global__ __launch_bounds__(256, 3) void kB(
    const int* __restrict__ ptw, const float* __restrict__ ept,
    const float* __restrict__ bb)
{
    float* sc   = smemB;
    ulonglong2* epsQ = (ulonglong2*)(smemB + 12800);  // [group*128 + a]
    float* sinv = smemB + 13824;
    float* bbs  = smemB + 13856;

    const int bx   = blockIdx.x;
    const int b    = bx / 50;
    const int pt   = bx - b * 50;
    const int t    = threadIdx.x;
    const int w    = t >> 5;
    const int lane = t & 31;

    {
        float* ef = (float*)epsQ;
        for (int i = t; i < 1024; i += 256) {
            int g  = i >> 9;
            int a  = (i >> 2) & 127;
            int c4 = i & 3;
            int pl = g * 2 + (c4 >> 1);
            ef[(g * 128 + a) * 4 + c4] = ept[(long)ptw[pt * PT + pl] * A_D + a];
        }
    }
    if (t < 8) bbs[t] = bb[t];
    __syncthreads();

    {
        const int pairI = w & 1;
        float* scA = sc + (2 * pairI + 0) * H_ * N_;
        float* scB = sc + (2 * pairI + 1) * H_ * N_;
        const char* epBase = (const char*)(epsQ + pairI * 128);

        for (int c = w >> 1; c < NCH; c += 4) {
            u64 accA[H_], accB[H_];
#pragma unroll
            for (int h = 0; h < H_; h++) { accA[h] = 0ull; accB[h] = 0ull; }

            const char* ppB = (const char*)(g_projP + ((b * NCH + c) * 64) * 32 + lane);
            const char* epB = epBase;

            u64 T0, T1, T2, T3, U0, U1, U2, U3;
            {
                ulonglong2 L0 = *(const ulonglong2*)ppB;
                STAGE_TANH(L0, epB, T0, T1, T2, T3);
            }
            ulonglong2 L1 = *(const ulonglong2*)(ppB + 512);
            ulonglong2 L2 = *(const ulonglong2*)(ppB + 1024);
            ppB += 1536;
            epB += 32;

            int wc = 0;
#pragma unroll 2
            for (int s = 0; s < 62; s++) {
                STAGE_TANH(L1, epB, U0, U1, U2, U3);
                STAGE_FMA(wc, T0, T1, T2, T3);
                L1 = L2;
                L2 = *(const ulonglong2*)ppB;
                T0 = U0; T1 = U1; T2 = U2; T3 = U3;
                ppB += 512;
                epB += 32;
                wc += 8;
            }
            STAGE_TANH(L1, epB, U0, U1, U2, U3);
            STAGE_FMA(wc, T0, T1, T2, T3);
            STAGE_FMA(wc + 8, U0, U1, U2, U3);

            int geneA, geneB;
            bool valid;
            if (c < 6) { geneA = c * 64 + lane; geneB = geneA + 32; valid = true; }
            else       { geneA = 384 + (lane & 7); geneB = geneA + 8; valid = (lane < 8); }
            if (valid) {
#pragma unroll
                for (int h = 0; h < H_; h++) {
                    float xA, yA, xB, yB;
                    unpack2(accA[h], xA, yA);
                    unpack2(accB[h], xB, yB);
                    const float bh = bbs[h];
                    scA[h * N_ + geneA] = xA + bh;
                    scA[h * N_ + geneB] = yA + bh;
                    scB[h * N_ + geneA] = xB + bh;
                    scB[h * N_ + geneB] = yB + bh;
                }
            }
        }
    }
    __syncthreads();

    const int p    = w >> 1;
    const int half = w & 1;
    const int pg   = pt * PT + p;
    float* scp = sc + p * H_ * N_;
#pragma unroll
    for (int q = 0; q < 4; q++) {
        const int h = half * 4 + q;
        float* row = scp + h * N_;
        float m = -1e30f;
        for (int i = lane; i < N_; i += 32) m = fmaxf(m, row[i]);
#pragma unroll
        for (int o = 16; o; o >>= 1) m = fmaxf(m, __shfl_xor_sync(0xffffffffu, m, o));
        float s = 0.f;
        for (int i = lane; i < N_; i += 32) {
            float e = __expf(row[i] - m);
            row[i] = e;
            s += e;
        }
#pragma unroll
        for (int o = 16; o; o >>= 1) s += __shfl_xor_sync(0xffffffffu, s, o);
        if (lane == 0) sinv[p * H_ + h] = __fdividef(1.f, s);
    }
    __syncthreads();

    {
        float iv[H_];
#pragma unroll
        for (int h = 0; h < H_; h++) iv[h] = sinv[p * H_ + h];
        float* gap = g_attn + ((long)(b * P_) + pg) * N_;
        for (int i = lane; i < 200; i += 32) {
            const int n = half * 200 + i;
            float a = 0.f;
#pragma unroll
            for (int h = 0; h < H_; h++) a = fmaf(scp[h * N_ + n], iv[h], a);
            gap[n] = a;
        }
    }
}

// ---------------------------------------------------------------------------
// Kernel C (pooling, v2): out[b,pg,:] = sum_n attn[b,pg,n] * E[b,n,:]
// Block = (b, 8 pathways), 256 threads = 8 warps.
// Warp = (quad q = w>>2: 4 pathways, gene-quarter gq = w&3).
// Per gene: ONE E-row read (2 LDS.128, 32+18 lanes) + 4 attn broadcasts
// feeds 16 fma2 (4 pathways) -> E-bytes reused 4x vs R12's 1x.
// Gene-quarter partials reduced via smem (Es region, free after the loop).
//
// SMEM floats:
//   Es    [0, 12800)       64 genes x 200 floats (= 3200 u128)
//   attnS [12800, 16000)   8 x 400
//   idxs  [16000, 16064)
// = 64256 bytes -> 3 blocks/SM
// ---------------------------------------------------------------------------
#define SMEM_C_FLOATS 16064
#define SMEM_C_BYTES  (SMEM_C_FLOATS * 4)

__global__ __launch_bounds__(256, 3) void kC(
    const int* __restrict__ omc, const float* __restrict__ eg,
    float* __restrict__ out)
{
    float* Es    = smemB;
    float* attnS = smemB + 12800;
    int*   idxs  = (int*)(smemB + 16000);

    const int bx   = blockIdx.x;
    const int b    = bx / 25;
    const int pt8  = bx - b * 25;       // pathway octet
    const int t    = threadIdx.x;
    const int w    = t >> 5;
    const int lane = t & 31;
    const int q    = w >> 2;            // pathway quad 0..1
    const int gq   = w & 3;             // gene quarter

    // stage attn for 8 pathways (3200 floats)
    {
        const float4* gA0 = (const float4*)(g_attn + ((long)(b * P_) + pt8 * 8) * N_);
        float4* aS = (float4*)attnS;
        for (int i = t; i < 800; i += 256) aS[i] = gA0[i];
    }

    const float* ap0 = attnS + (q * 4 + 0) * N_;
    const float* ap1 = attnS + (q * 4 + 1) * N_;
    const float* ap2 = attnS + (q * 4 + 2) * N_;
    const float* ap3 = attnS + (q * 4 + 3) * N_;

    const ulonglong2* egq = (const ulonglong2*)eg;   // 50 u128 per vocab row
    ulonglong2* Esq = (ulonglong2*)Es;               // 3200 u128

    // accs: pathway p (0..3 in quad) x 4 u64 (u128 slots lane / 32+lane)
    u64 a00=0, a01=0, a02=0, a03=0;
    u64 a10=0, a11=0, a12=0, a13=0;
    u64 a20=0, a21=0, a22=0, a23=0;
    u64 a30=0, a31=0, a32=0, a33=0;

    for (int c = 0; c < NCH; c++) {
        const int n0 = c * 64;
        const int cnt = min(64, N_ - n0);
        __syncthreads();
        if (t < cnt) idxs[t] = omc[b * N_ + n0 + t];
        __syncthreads();
        // stage E rows: warp w stages genes w, w+8, ... (no division)
        for (int g = w; g < cnt; g += 8) {
            const ulonglong2* src = egq + (long)idxs[g] * 50;
            ulonglong2* dst = Esq + g * 50;
            dst[lane] = src[lane];
            if (lane < 18) dst[32 + lane] = src[32 + lane];
        }
        __syncthreads();

        for (int n = gq; n < cnt; n += 4) {
            const int na = n0 + n;
            u64 v0 = pack2(ap0[na], ap0[na]);
            u64 v1 = pack2(ap1[na], ap1[na]);
            u64 v2 = pack2(ap2[na], ap2[na]);
            u64 v3 = pack2(ap3[na], ap3[na]);
            ulonglong2 e0 = Esq[n * 50 + lane];
            a00 = fma2(e0.x, v0, a00);  a01 = fma2(e0.y, v0, a01);
            a10 = fma2(e0.x, v1, a10);  a11 = fma2(e0.y, v1, a11);
            a20 = fma2(e0.x, v2, a20);  a21 = fma2(e0.y, v2, a21);
            a30 = fma2(e0.x, v3, a30);  a31 = fma2(e0.y, v3, a31);
            if (lane < 18) {
                ulonglong2 e1 = Esq[n * 50 + 32 + lane];
                a02 = fma2(e1.x, v0, a02);  a03 = fma2(e1.y, v0, a03);
                a12 = fma2(e1.x, v1, a12);  a13 = fma2(e1.y, v1, a13);
                a22 = fma2(e1.x, v2, a22);  a23 = fma2(e1.y, v2, a23);
                a32 = fma2(e1.x, v3, a32);  a33 = fma2(e1.y, v3, a33);
            }
        }
    }
    __syncthreads();   // Es region free; reuse for reduction

    // reduction over gene-quarters: gq 1..3 store, gq 0 accumulates + writes.
    // red layout: [(q*3 + (gq-1))*4 + p] rows of 50 u128 -> 24 rows x 50 = 1200 u128
    ulonglong2* red = Esq;
    if (gq != 0) {
        ulonglong2* r0 = red + ((q * 3 + (gq - 1)) * 4 + 0) * 50;
        ulonglong2* r1 = red + ((q * 3 + (gq - 1)) * 4 + 1) * 50;
        ulonglong2* r2 = red + ((q * 3 + (gq - 1)) * 4 + 2) * 50;
        ulonglong2* r3 = red + ((q * 3 + (gq - 1)) * 4 + 3) * 50;
        ulonglong2 s;
        s.x = a00; s.y = a01; r0[lane] = s;
        s.x = a10; s.y = a11; r1[lane] = s;
        s.x = a20; s.y = a21; r2[lane] = s;
        s.x = a30; s.y = a31; r3[lane] = s;
        if (lane < 18) {
            s.x = a02; s.y = a03; r0[32 + lane] = s;
            s.x = a12; s.y = a13; r1[32 + lane] = s;
            s.x = a22; s.y = a23; r2[32 + lane] = s;
            s.x = a32; s.y = a33; r3[32 + lane] = s;
        }
    }
    __syncthreads();
    if (gq == 0) {
#pragma unroll
        for (int j = 0; j < 3; j++) {
            const ulonglong2* r0 = red + ((q * 3 + j) * 4 + 0) * 50;
            const ulonglong2* r1 = red + ((q * 3 + j) * 4 + 1) * 50;
            const ulonglong2* r2 = red + ((q * 3 + j) * 4 + 2) * 50;
            const ulonglong2* r3 = red + ((q * 3 + j) * 4 + 3) * 50;
            ulonglong2 s;
            s = r0[lane]; a00 = add2(a00, s.x); a01 = add2(a01, s.y);
            s = r1[lane]; a10 = add2(a10, s.x); a11 = add2(a11, s.y);
            s = r2[lane]; a20 = add2(a20, s.x); a21 = add2(a21, s.y);
            s = r3[lane]; a30 = add2(a30, s.x); a31 = add2(a31, s.y);
            if (lane < 18) {
                s = r0[32 + lane]; a02 = add2(a02, s.x); a03 = add2(a03, s.y);
                s = r1[32 + lane]; a12 = add2(a12, s.x); a13 = add2(a13, s.y);
                s = r2[32 + lane]; a22 = add2(a22, s.x); a23 = add2(a23, s.y);
                s = r3[32 + lane]; a32 = add2(a32, s.x); a33 = add2(a33, s.y);
            }
        }
        const int pg0 = pt8 * 8 + q * 4;
        ulonglong2* op0 = (ulonglong2*)(out + (long)(b * P_ + pg0 + 0) * E_D);
        ulonglong2* op1 = (ulonglong2*)(out + (long)(b * P_ + pg0 + 1) * E_D);
        ulonglong2* op2 = (ulonglong2*)(out + (long)(b * P_ + pg0 + 2) * E_D);
        ulonglong2* op3 = (ulonglong2*)(out + (long)(b * P_ + pg0 + 3) * E_D);
        ulonglong2 s;
        s.x = a00; s.y = a01; op0[lane] = s;
        s.x = a10; s.y = a11; op1[lane] = s;
        s.x = a20; s.y = a21; op2[lane] = s;
        s.x = a30; s.y = a31; op3[lane] = s;
        if (lane < 18) {
            s.x = a02; s.y = a03; op0[32 + lane] = s;
            s.x = a12; s.y = a13; op1[32 + lane] = s;
            s.x = a22; s.y = a23; op2[32 + lane] = s;
            s.x = a32; s.y = a33; op3[32 + lane] = s;
        }
    }
}

// ---------------------------------------------------------------------------
extern "C" void kernel_launch(void* const* d_in, const int* in_sizes, int n_in,
                              void* d_out, int out_size)
{
    const int*   omc = (const int*)  d_in[0];
    const int*   ptw = (const int*)  d_in[1];
    const float* eg  = (const float*)d_in[2];
    const float* ept = (const float*)d_in[3];
    const float* W0  = (const float*)d_in[4];
    const float* b0  = (const float*)d_in[5];
    const float* Wb  = (const float*)d_in[6];
    const float* bb  = (const float*)d_in[7];
    float* out = (float*)d_out;

    kW<<<4, 256>>>(Wb);
    void* srcp = nullptr;
    cudaGetSymbolAddress(&srcp, g_wbDup);
    void* dstp = nullptr;
    cudaGetSymbolAddress(&dstp, c_wb4);
    cudaMemcpyAsync(dstp, srcp, sizeof(u64) * A_D * H_,
                    cudaMemcpyDeviceToDevice, 0);

    kA<<<(B_ * N_) / 8, 128>>>(omc, eg, W0, b0);

    cudaFuncSetAttribute(kB, cudaFuncAttributeMaxDynamicSharedMemorySize,
                         SMEM_B_BYTES);
    kB<<<B_ * (P_ / PT), 256, SMEM_B_BYTES>>>(ptw, ept, bb);

    cudaFuncSetAttribute(kC, cudaFuncAttributeMaxDynamicSharedMemorySize,
                         SMEM_C_BYTES);
    kC<<<B_ * (P_ / 8), 256, SMEM_C_BYTES>>>(omc, eg, out);
}